// round 1
// baseline (speedup 1.0000x reference)
#include <cuda_runtime.h>
#include <cuda_bf16.h>
#include <cstdint>

// out[s,a] = values[index[s,a]]
// index: int32 [16384, 2048] (in_sizes[0] = 33554432)
// values: float [100]
// out: float [16384*2048]
//
// Pure HBM-bound gather. Strategy:
//  - stage the 100-entry values table in shared memory
//  - int4 loads of indices, float4 stores of output (16B transactions)

static constexpr int VOCAB_MAX = 128;   // table is 100 entries; pad smem to 128

__global__ void __launch_bounds__(256) gather_vec4_kernel(
    const int4* __restrict__ idx4,
    const float* __restrict__ values,
    float4* __restrict__ out4,
    int n_vec4,
    int n_values)
{
    __shared__ float s_vals[VOCAB_MAX];
    // cooperative load of the tiny table
    for (int i = threadIdx.x; i < n_values; i += blockDim.x) {
        s_vals[i] = values[i];
    }
    __syncthreads();

    int i = blockIdx.x * blockDim.x + threadIdx.x;
    if (i < n_vec4) {
        int4 idx = idx4[i];
        float4 r;
        r.x = s_vals[idx.x];
        r.y = s_vals[idx.y];
        r.z = s_vals[idx.z];
        r.w = s_vals[idx.w];
        out4[i] = r;
    }
}

// Fallback for non-multiple-of-4 tails (not expected here, but safe).
__global__ void gather_tail_kernel(
    const int* __restrict__ idx,
    const float* __restrict__ values,
    float* __restrict__ out,
    int start,
    int n_total)
{
    int i = start + blockIdx.x * blockDim.x + threadIdx.x;
    if (i < n_total) {
        out[i] = values[idx[i]];
    }
}

extern "C" void kernel_launch(void* const* d_in, const int* in_sizes, int n_in,
                              void* d_out, int out_size)
{
    const int* index = (const int*)d_in[0];
    const float* values = (const float*)d_in[1];
    float* out = (float*)d_out;

    int n_total = in_sizes[0];          // 16384 * 2048 = 33,554,432
    int n_values = in_sizes[1];         // 100
    int n_vec4 = n_total / 4;           // 8,388,608

    const int threads = 256;
    int blocks = (n_vec4 + threads - 1) / threads;
    gather_vec4_kernel<<<blocks, threads>>>(
        (const int4*)index, values, (float4*)out, n_vec4, n_values);

    int tail_start = n_vec4 * 4;
    int tail = n_total - tail_start;
    if (tail > 0) {
        int tb = (tail + threads - 1) / threads;
        gather_tail_kernel<<<tb, threads>>>(index, values, out, tail_start, n_total);
    }
}

// round 2
// speedup vs baseline: 1.0163x; 1.0163x over previous
#include <cuda_runtime.h>
#include <cuda_bf16.h>
#include <cstdint>

// out[s,a] = values[index[s,a]]
// index: int32 [33,554,432], values: float [100], out: float [33,554,432]
//
// HBM-bound gather at the LTS cap. Strategy:
//  - 100-entry table staged in smem
//  - each thread does 4 independent front-batched int4 loads (MLP=4)
//  - streaming cache hints: __ldcs for index (read-once), __stcs for out (write-once)

static constexpr int VOCAB_MAX = 128;
static constexpr int THREADS   = 256;
static constexpr int VEC_PER_THREAD = 4;           // 4 x int4 = 16 elements/thread
static constexpr int VEC_PER_BLOCK  = THREADS * VEC_PER_THREAD;  // 1024 vec4 / block

__global__ void __launch_bounds__(THREADS) gather_vec4x4_kernel(
    const int4* __restrict__ idx4,
    const float* __restrict__ values,
    float4* __restrict__ out4,
    int n_vec4,
    int n_values)
{
    __shared__ float s_vals[VOCAB_MAX];
    for (int i = threadIdx.x; i < n_values; i += THREADS) {
        s_vals[i] = values[i];
    }
    __syncthreads();

    int base = blockIdx.x * VEC_PER_BLOCK + threadIdx.x;

    // Fast path: block fully in range (true for all blocks when n is a
    // multiple of VEC_PER_BLOCK, which it is here: 8,388,608 / 1024 = 8192).
    if (base + (VEC_PER_THREAD - 1) * THREADS < n_vec4) {
        int4 v[VEC_PER_THREAD];
        // Front-batched independent loads -> MLP = 4
        #pragma unroll
        for (int k = 0; k < VEC_PER_THREAD; k++) {
            v[k] = __ldcs(&idx4[base + k * THREADS]);
        }
        #pragma unroll
        for (int k = 0; k < VEC_PER_THREAD; k++) {
            float4 r;
            r.x = s_vals[v[k].x];
            r.y = s_vals[v[k].y];
            r.z = s_vals[v[k].z];
            r.w = s_vals[v[k].w];
            __stcs(&out4[base + k * THREADS], r);
        }
    } else {
        // Tail path (not hit for this shape, kept for safety)
        #pragma unroll
        for (int k = 0; k < VEC_PER_THREAD; k++) {
            int i = base + k * THREADS;
            if (i < n_vec4) {
                int4 v = __ldcs(&idx4[i]);
                float4 r;
                r.x = s_vals[v.x];
                r.y = s_vals[v.y];
                r.z = s_vals[v.z];
                r.w = s_vals[v.w];
                __stcs(&out4[i], r);
            }
        }
    }
}

__global__ void gather_tail_kernel(
    const int* __restrict__ idx,
    const float* __restrict__ values,
    float* __restrict__ out,
    int start,
    int n_total)
{
    int i = start + blockIdx.x * blockDim.x + threadIdx.x;
    if (i < n_total) {
        out[i] = values[idx[i]];
    }
}

extern "C" void kernel_launch(void* const* d_in, const int* in_sizes, int n_in,
                              void* d_out, int out_size)
{
    const int* index = (const int*)d_in[0];
    const float* values = (const float*)d_in[1];
    float* out = (float*)d_out;

    int n_total = in_sizes[0];          // 33,554,432
    int n_values = in_sizes[1];         // 100
    int n_vec4 = n_total / 4;           // 8,388,608

    int blocks = (n_vec4 + VEC_PER_BLOCK - 1) / VEC_PER_BLOCK;  // 8192
    gather_vec4x4_kernel<<<blocks, THREADS>>>(
        (const int4*)index, values, (float4*)out, n_vec4, n_values);

    int tail_start = n_vec4 * 4;
    int tail = n_total - tail_start;
    if (tail > 0) {
        int tb = (tail + 255) / 256;
        gather_tail_kernel<<<tb, 256>>>(index, values, out, tail_start, n_total);
    }
}